// round 1
// baseline (speedup 1.0000x reference)
#include <cuda_runtime.h>
#include <math.h>
#include <stdint.h>

// ---------------------------------------------------------------------------
// DDDDepthDiff: fused depth losses + RANSAC plane fit (JAX reference port)
// ---------------------------------------------------------------------------

#define JAX_PARTITIONABLE 1   // JAX >= 0.4.36 default threefry mode; flip to 0 if RANSAC outputs mismatch

#define HW       230400       // 360*640
#define WIDTH    640
#define NPLANES  1000
#define MINPTS   5000
#define SPAN     230400u

#define K1_BLOCKS 240
#define K3_BLOCKS 450
#define K3_CHUNK  512         // 450*512 == 230400 exactly
#define K3_THREADS 256
#define PPT       4           // planes per thread (256*4 = 1024 >= 1000)

// ----------------------------- scratch ------------------------------------
__device__ float g_cx[HW];
__device__ float g_cy[HW];
__device__ float g_cz[HW];
__device__ float4 g_planes[NPLANES];
__device__ unsigned g_counts[NPLANES];

struct Accum {
    double sumX, sumY, sumZ, sumLog;
    unsigned long long cntM;
    int gmaxBits;                 // max of non-negative floats (raw-bit atomicMax valid)
    unsigned zmaxEnc, zminEnc;    // order-encoded floats
    unsigned long long icnt;
    double sumBelow, sumAbove;
    int best;
    float4 bestPlane;
    float R20, R21, R22, dz, thresh;
};
__device__ Accum g_acc;

// ----------------------------- helpers ------------------------------------
__device__ __forceinline__ unsigned encf(float f) {
    unsigned u = __float_as_uint(f);
    return (u & 0x80000000u) ? ~u : (u | 0x80000000u);
}
__device__ __forceinline__ float decf(unsigned e) {
    return (e & 0x80000000u) ? __uint_as_float(e ^ 0x80000000u) : __uint_as_float(~e);
}

__device__ __forceinline__ double wred_add_d(double v) {
    #pragma unroll
    for (int o = 16; o; o >>= 1) v += __shfl_down_sync(0xffffffffu, v, o);
    return v;
}
__device__ __forceinline__ unsigned long long wred_add_u(unsigned long long v) {
    #pragma unroll
    for (int o = 16; o; o >>= 1) v += __shfl_down_sync(0xffffffffu, v, o);
    return v;
}
__device__ __forceinline__ float wred_max_f(float v) {
    #pragma unroll
    for (int o = 16; o; o >>= 1) v = fmaxf(v, __shfl_down_sync(0xffffffffu, v, o));
    return v;
}
__device__ __forceinline__ float wred_min_f(float v) {
    #pragma unroll
    for (int o = 16; o; o >>= 1) v = fminf(v, __shfl_down_sync(0xffffffffu, v, o));
    return v;
}

// threefry-2x32, exactly as jax._src.prng._threefry2x32
__device__ __forceinline__ void tf2x32(unsigned k0, unsigned k1, unsigned& x0, unsigned& x1) {
    unsigned ks[3] = { k0, k1, 0x1BD11BDAu ^ k0 ^ k1 };
    const unsigned rotA[4] = { 13u, 15u, 26u, 6u };
    const unsigned rotB[4] = { 17u, 29u, 16u, 24u };
    x0 += ks[0]; x1 += ks[1];
    #pragma unroll
    for (int i = 0; i < 5; ++i) {
        #pragma unroll
        for (int j = 0; j < 4; ++j) {
            unsigned r = ((i & 1) == 0) ? rotA[j] : rotB[j];
            x0 += x1;
            x1 = (x1 << r) | (x1 >> (32u - r));
            x1 ^= x0;
        }
        x0 += ks[(i + 1) % 3];
        x1 += ks[(i + 2) % 3] + (unsigned)(i + 1);
    }
}

#if !JAX_PARTITIONABLE
// original-mode random_bits for a flat array of 3000 elements (split 1500/1500)
__device__ __forceinline__ unsigned bits_orig(unsigned k0, unsigned k1, unsigned i) {
    unsigned x0, x1;
    bool first = i < 1500u;
    if (first) { x0 = i; x1 = i + 1500u; } else { x0 = i - 1500u; x1 = i; }
    tf2x32(k0, k1, x0, x1);
    return first ? x0 : x1;
}
#endif

// Shared inlier predicate — MUST be identical between counting and mask kernels.
__device__ __forceinline__ float plane_dist(float4 pl, float px, float py, float pz) {
    return __fmaf_rn(pl.x, px, __fmaf_rn(pl.y, py, __fmaf_rn(pl.z, pz, pl.w)));
}

// ----------------------------- kernels ------------------------------------
__global__ void k0_init(const int* __restrict__ epoch_ptr) {
    int t = threadIdx.x;
    for (int i = t; i < NPLANES; i += blockDim.x) g_counts[i] = 0u;
    if (t == 0) {
        g_acc.sumX = 0.0; g_acc.sumY = 0.0; g_acc.sumZ = 0.0; g_acc.sumLog = 0.0;
        g_acc.cntM = 0ull;
        g_acc.gmaxBits = 0;
        g_acc.zmaxEnc = 0x007FFFFFu;   // enc(-inf)
        g_acc.zminEnc = 0xFF800000u;   // enc(+inf)
        g_acc.icnt = 0ull;
        g_acc.sumBelow = 0.0; g_acc.sumAbove = 0.0;
        int epoch = epoch_ptr[0];
        float thf = (float)(0.025 - 0.001 * (double)epoch);
        g_acc.thresh = fmaxf(thf, 0.005f);
    }
}

__global__ void k1_stats(const float* __restrict__ fake, const float* __restrict__ real) {
    double sX = 0.0, sY = 0.0, sZ = 0.0, sL = 0.0;
    unsigned long long c = 0ull;
    float mx = 0.0f;
    for (int i = blockIdx.x * blockDim.x + threadIdx.x; i < HW; i += gridDim.x * blockDim.x) {
        int r = i / WIDTH;
        int col = i - r * WIDTH;
        float cc = (float)col - 334.081f;
        float rr = (float)r - 169.808f;
        float dr = real[i], df = fake[i];
        bool vr = (dr > 0.0f) && (dr < 65535.0f);
        bool vf = (df > 0.0f) && (df < 65535.0f);

        // fake cloud (replicates: z=d/1000; x=(z*cc)/FX; then *1000; ==0 -> eps; nan -> 0)
        float fz = df / 1000.0f;
        float fxp = (fz * cc) / 460.585f;
        float fyp = (fz * rr) / 460.268f;
        float FXv = fxp * 1000.0f, FYv = fyp * 1000.0f, FZv = fz * 1000.0f;
        if (FXv == 0.0f) FXv = 1e-7f;
        if (FYv == 0.0f) FYv = 1e-7f;
        if (FZv == 0.0f) FZv = 1e-7f;
        float ox = vf ? FXv : 0.0f;
        float oy = vf ? FYv : 0.0f;
        float oz = vf ? FZv : 0.0f;
        g_cx[i] = ox; g_cy[i] = oy; g_cz[i] = oz;
        mx = fmaxf(mx, fmaxf(ox, fmaxf(oy, oz)));

        if (vr && vf) {
            float rz = dr / 1000.0f;
            float rxp = (rz * cc) / 460.585f;
            float ryp = (rz * rr) / 460.268f;
            float RXv = rxp * 1000.0f, RYv = ryp * 1000.0f, RZv = rz * 1000.0f;
            if (RXv == 0.0f) RXv = 1e-7f;
            if (RYv == 0.0f) RYv = 1e-7f;
            if (RZv == 0.0f) RZv = 1e-7f;
            float dx = RXv - FXv, dy = RYv - FYv, dz = RZv - FZv;
            sX += (double)dx * (double)dx;
            sY += (double)dy * (double)dy;
            sZ += (double)dz * (double)dz;
            float dl = logf(fabsf(RZv)) - logf(fabsf(FZv));
            sL += (double)dl * (double)dl;
            c++;
        }
    }
    sX = wred_add_d(sX); sY = wred_add_d(sY); sZ = wred_add_d(sZ); sL = wred_add_d(sL);
    c = wred_add_u(c);
    mx = wred_max_f(mx);
    if ((threadIdx.x & 31) == 0) {
        atomicAdd(&g_acc.sumX, sX);
        atomicAdd(&g_acc.sumY, sY);
        atomicAdd(&g_acc.sumZ, sZ);
        atomicAdd(&g_acc.sumLog, sL);
        atomicAdd(&g_acc.cntM, c);
        atomicMax(&g_acc.gmaxBits, __float_as_int(mx));  // mx >= 0 always
    }
}

__global__ void k2_planes() {
    int t = blockIdx.x * blockDim.x + threadIdx.x;
    if (t >= NPLANES) return;

    // key(42) -> (0, 42); split(key) -> k1, k2 per JAX mode
    unsigned k10, k11, k20, k21;
#if JAX_PARTITIONABLE
    { unsigned x0 = 0u, x1 = 0u; tf2x32(0u, 42u, x0, x1); k10 = x0; k11 = x1; }
    { unsigned x0 = 0u, x1 = 1u; tf2x32(0u, 42u, x0, x1); k20 = x0; k21 = x1; }
#else
    {
        unsigned a0 = 0u, a1 = 2u; tf2x32(0u, 42u, a0, a1);  // pair (0,2)
        unsigned b0 = 1u, b1 = 3u; tf2x32(0u, 42u, b0, b1);  // pair (1,3)
        k10 = a0; k11 = b0;   // k1 = (out_x0[0], out_x0[1])
        k20 = a1; k21 = b1;   // k2 = (out_x1[0], out_x1[1])
    }
#endif
    unsigned span = SPAN;
    unsigned mult = 65536u % span;
    mult = (mult * mult) % span;   // uint32 wrap — matches JAX exactly (0 for this span)

    int ids[3];
    #pragma unroll
    for (int j = 0; j < 3; ++j) {
        unsigned i = (unsigned)(t * 3 + j);
        unsigned hi, lo;
#if JAX_PARTITIONABLE
        { unsigned x0 = 0u, x1 = i; tf2x32(k10, k11, x0, x1); hi = x0 ^ x1; }
        { unsigned x0 = 0u, x1 = i; tf2x32(k20, k21, x0, x1); lo = x0 ^ x1; }
#else
        hi = bits_orig(k10, k11, i);
        lo = bits_orig(k20, k21, i);
#endif
        unsigned off = ((hi % span) * mult + (lo % span)) % span;
        ids[j] = (int)off;
    }

    float gmax = __int_as_float(g_acc.gmaxBits);
    float p0x = g_cx[ids[0]] / gmax, p0y = g_cy[ids[0]] / gmax, p0z = g_cz[ids[0]] / gmax;
    float p1x = g_cx[ids[1]] / gmax, p1y = g_cy[ids[1]] / gmax, p1z = g_cz[ids[1]] / gmax;
    float p2x = g_cx[ids[2]] / gmax, p2y = g_cy[ids[2]] / gmax, p2z = g_cz[ids[2]] / gmax;

    float ax = p1x - p0x, ay = p1y - p0y, az = p1z - p0z;
    float bx = p2x - p0x, by = p2y - p0y, bz = p2z - p0z;
    float nx = ay * bz - az * by;
    float ny = az * bx - ax * bz;
    float nz = ax * by - ay * bx;
    float nn = sqrtf(nx * nx + ny * ny + nz * nz);
    nx /= nn; ny /= nn; nz /= nn;
    float kk = -(nx * p1x + ny * p1y + nz * p1z);
    g_planes[t] = make_float4(nx, ny, nz, kk);
}

__global__ __launch_bounds__(K3_THREADS) void k3_count() {
    __shared__ float4 spt[K3_CHUNK];
    int base = blockIdx.x * K3_CHUNK;
    float gmax = __int_as_float(g_acc.gmaxBits);
    float th = g_acc.thresh;

    for (int j = threadIdx.x; j < K3_CHUNK; j += K3_THREADS) {
        int i = base + j;
        spt[j] = make_float4(g_cx[i] / gmax, g_cy[i] / gmax, g_cz[i] / gmax, 0.0f);
    }

    float4 pl[PPT];
    int cnt[PPT];
    #pragma unroll
    for (int k = 0; k < PPT; ++k) {
        int pid = threadIdx.x + k * K3_THREADS;
        pl[k] = (pid < NPLANES) ? g_planes[pid] : make_float4(0.0f, 0.0f, 0.0f, 1e30f);
        cnt[k] = 0;
    }
    __syncthreads();

    #pragma unroll 4
    for (int j = 0; j < K3_CHUNK; ++j) {
        float4 p = spt[j];
        #pragma unroll
        for (int k = 0; k < PPT; ++k) {
            float d = plane_dist(pl[k], p.x, p.y, p.z);
            cnt[k] += (fabsf(d) <= th) ? 1 : 0;
        }
    }

    #pragma unroll
    for (int k = 0; k < PPT; ++k) {
        int pid = threadIdx.x + k * K3_THREADS;
        if (pid < NPLANES) atomicAdd(&g_counts[pid], (unsigned)cnt[k]);
    }
}

__global__ void k4_select() {
    __shared__ int skey[1024];
    int t = threadIdx.x;
    int key = -1;
    if (t < NPLANES) {
        int c = (int)g_counts[t];
        int score = (c > MINPTS) ? c : -1;
        key = ((score + 1) << 12) | (1023 - t);   // first-index tiebreak
    }
    skey[t] = key;
    __syncthreads();
    for (int s = 512; s > 0; s >>= 1) {
        if (t < s) skey[t] = max(skey[t], skey[t + s]);
        __syncthreads();
    }
    if (t == 0) {
        int mk = skey[0];
        int best = 1023 - (mk & 0xFFF);
        g_acc.best = best;
        float4 bp = g_planes[best];
        g_acc.bestPlane = bp;
        float a = bp.x, b = bp.y, c = bp.z, d = bp.w;
        float n2 = a * a + b * b + c * c;
        float cos_t = c / sqrtf(n2);
        float sin_t = sqrtf((a * a + b * b) / n2);
        float sab = sqrtf(a * a + b * b);
        float u1 = b / sab;
        float u2 = -a / sab;
        g_acc.dz = d / c;
        g_acc.R20 = -u2 * sin_t;
        g_acc.R21 = u1 * sin_t;
        g_acc.R22 = cos_t;
    }
}

__global__ void k5a_minmax() {
    float gmax = __int_as_float(g_acc.gmaxBits);
    float th = g_acc.thresh;
    float4 bp = g_acc.bestPlane;
    float R20 = g_acc.R20, R21 = g_acc.R21, R22 = g_acc.R22, dz = g_acc.dz;
    const float INF = __int_as_float(0x7f800000);
    float zmx = -INF, zmn = INF;
    unsigned long long ic = 0ull;
    for (int i = blockIdx.x * blockDim.x + threadIdx.x; i < HW; i += gridDim.x * blockDim.x) {
        float px = g_cx[i] / gmax, py = g_cy[i] / gmax, pz = g_cz[i] / gmax;
        float d = plane_dist(bp, px, py, pz);
        if (fabsf(d) <= th) {
            float zc = __fmaf_rn(pz + dz, R22, __fmaf_rn(py, R21, px * R20));
            zmx = fmaxf(zmx, zc);
            zmn = fminf(zmn, zc);
            ic++;
        }
    }
    zmx = wred_max_f(zmx);
    zmn = wred_min_f(zmn);
    ic = wred_add_u(ic);
    if ((threadIdx.x & 31) == 0) {
        atomicMax(&g_acc.zmaxEnc, encf(zmx));
        atomicMin(&g_acc.zminEnc, encf(zmn));
        atomicAdd(&g_acc.icnt, ic);
    }
}

__global__ void k5b_sums() {
    float gmax = __int_as_float(g_acc.gmaxBits);
    float th = g_acc.thresh;
    float4 bp = g_acc.bestPlane;
    float R20 = g_acc.R20, R21 = g_acc.R21, R22 = g_acc.R22, dz = g_acc.dz;
    float zmax = decf(g_acc.zmaxEnc);
    float zmin = decf(g_acc.zminEnc);
    double sB = 0.0, sA = 0.0;
    for (int i = blockIdx.x * blockDim.x + threadIdx.x; i < HW; i += gridDim.x * blockDim.x) {
        float px = g_cx[i] / gmax, py = g_cy[i] / gmax, pz = g_cz[i] / gmax;
        float d = plane_dist(bp, px, py, pz);
        if (fabsf(d) <= th) {
            float zc = __fmaf_rn(pz + dz, R22, __fmaf_rn(py, R21, px * R20));
            sB += (double)fabsf(zc - zmax);
            sA += (double)fabsf(zc - zmin);
        }
    }
    sB = wred_add_d(sB);
    sA = wred_add_d(sA);
    if ((threadIdx.x & 31) == 0) {
        atomicAdd(&g_acc.sumBelow, sB);
        atomicAdd(&g_acc.sumAbove, sA);
    }
}

__global__ void k6_final(float* __restrict__ out, int out_size) {
    unsigned long long cm = g_acc.cntM; if (cm < 1) cm = 1;
    double cnt = (double)cm;
    float lX = (float)sqrt(g_acc.sumX / cnt);
    float lY = (float)sqrt(g_acc.sumY / cnt);
    float lZ = (float)sqrt(g_acc.sumZ / cnt);
    float rmse_log = (float)(10000.0 * sqrt(g_acc.sumLog / cnt));
    float loss17 = rmse_log * fabsf(10.0f * (3.0f - expf(lX) - expf(lY) - expf(lZ)));

    unsigned long long icu = g_acc.icnt; if (icu < 1) icu = 1;
    double icnt = (double)icu;
    float below = (float)(g_acc.sumBelow / icnt);
    float above = (float)(g_acc.sumAbove / icnt);
    if (above == 0.0f) above = 1e-7f;
    float pmdg = 1000.0f * (above + below);
    float loss_curv = loss17 + pmdg;

    float vals[7] = { rmse_log, lX, lY, lZ, pmdg, loss17, loss_curv };
    for (int i = 0; i < 7 && i < out_size; ++i) out[i] = vals[i];
}

// ----------------------------- launch -------------------------------------
extern "C" void kernel_launch(void* const* d_in, const int* in_sizes, int n_in,
                              void* d_out, int out_size) {
    const float* fake = (const float*)d_in[0];
    const float* real = (const float*)d_in[1];
    const int* epoch = (const int*)d_in[2];
    (void)in_sizes; (void)n_in;

    k0_init<<<1, 1024>>>(epoch);
    k1_stats<<<K1_BLOCKS, 256>>>(fake, real);
    k2_planes<<<(NPLANES + 255) / 256, 256>>>();
    k3_count<<<K3_BLOCKS, K3_THREADS>>>();
    k4_select<<<1, 1024>>>();
    k5a_minmax<<<K1_BLOCKS, 256>>>();
    k5b_sums<<<K1_BLOCKS, 256>>>();
    k6_final<<<1, 1>>>((float*)d_out, out_size);
}

// round 2
// speedup vs baseline: 1.2773x; 1.2773x over previous
#include <cuda_runtime.h>
#include <math.h>
#include <stdint.h>

// ---------------------------------------------------------------------------
// DDDDepthDiff: fused depth losses + RANSAC plane fit (JAX reference port)
// R2: packed f32x2 inlier counting, occupancy fix, k5b eliminated analytically
// ---------------------------------------------------------------------------

#define HW       230400       // 360*640
#define WIDTH    640
#define NPLANES  1000
#define MINPTS   5000
#define SPAN     230400u

#define K1_BLOCKS 240
#define K3_CHUNK   512        // points per block (450 * 512 == 230400)
#define K3_XBLOCKS (HW / K3_CHUNK)
#define K3_YBLOCKS 2          // plane groups of 512
#define K3_THREADS 256
#define PPT        2          // planes per thread (256*2 = 512 per group)

typedef unsigned long long u64;

// ----------------------------- scratch ------------------------------------
__device__ float g_cx[HW];
__device__ float g_cy[HW];
__device__ float g_cz[HW];
__device__ float4 g_planes[NPLANES];
__device__ unsigned g_counts[NPLANES];

struct Accum {
    double sumX, sumY, sumZ, sumLog;
    unsigned long long cntM;
    int gmaxBits;                 // max of non-negative floats (raw-bit atomicMax valid)
    unsigned zmaxEnc, zminEnc;    // order-encoded floats
    unsigned long long icnt;
    double sumZc;
    int best;
    float4 bestPlane;
    float R20, R21, R22, dz, thresh;
};
__device__ Accum g_acc;

// ----------------------------- helpers ------------------------------------
__device__ __forceinline__ unsigned encf(float f) {
    unsigned u = __float_as_uint(f);
    return (u & 0x80000000u) ? ~u : (u | 0x80000000u);
}
__device__ __forceinline__ float decf(unsigned e) {
    return (e & 0x80000000u) ? __uint_as_float(e ^ 0x80000000u) : __uint_as_float(~e);
}

__device__ __forceinline__ double wred_add_d(double v) {
    #pragma unroll
    for (int o = 16; o; o >>= 1) v += __shfl_down_sync(0xffffffffu, v, o);
    return v;
}
__device__ __forceinline__ unsigned long long wred_add_u(unsigned long long v) {
    #pragma unroll
    for (int o = 16; o; o >>= 1) v += __shfl_down_sync(0xffffffffu, v, o);
    return v;
}
__device__ __forceinline__ float wred_max_f(float v) {
    #pragma unroll
    for (int o = 16; o; o >>= 1) v = fmaxf(v, __shfl_down_sync(0xffffffffu, v, o));
    return v;
}
__device__ __forceinline__ float wred_min_f(float v) {
    #pragma unroll
    for (int o = 16; o; o >>= 1) v = fminf(v, __shfl_down_sync(0xffffffffu, v, o));
    return v;
}

// packed f32x2 ops (sm_103a FFMA2 path — only reachable via PTX)
__device__ __forceinline__ u64 pack2(float lo, float hi) {
    u64 r; asm("mov.b64 %0, {%1, %2};" : "=l"(r) : "f"(lo), "f"(hi)); return r;
}
__device__ __forceinline__ u64 fma2(u64 a, u64 b, u64 c) {
    u64 d; asm("fma.rn.f32x2 %0, %1, %2, %3;" : "=l"(d) : "l"(a), "l"(b), "l"(c)); return d;
}
__device__ __forceinline__ void unpack2(u64 v, unsigned& lo, unsigned& hi) {
    asm("mov.b64 {%0, %1}, %2;" : "=r"(lo), "=r"(hi) : "l"(v));
}

// threefry-2x32, exactly as jax._src.prng._threefry2x32 (partitionable mode)
__device__ __forceinline__ void tf2x32(unsigned k0, unsigned k1, unsigned& x0, unsigned& x1) {
    unsigned ks[3] = { k0, k1, 0x1BD11BDAu ^ k0 ^ k1 };
    const unsigned rotA[4] = { 13u, 15u, 26u, 6u };
    const unsigned rotB[4] = { 17u, 29u, 16u, 24u };
    x0 += ks[0]; x1 += ks[1];
    #pragma unroll
    for (int i = 0; i < 5; ++i) {
        #pragma unroll
        for (int j = 0; j < 4; ++j) {
            unsigned r = ((i & 1) == 0) ? rotA[j] : rotB[j];
            x0 += x1;
            x1 = (x1 << r) | (x1 >> (32u - r));
            x1 ^= x0;
        }
        x0 += ks[(i + 1) % 3];
        x1 += ks[(i + 2) % 3] + (unsigned)(i + 1);
    }
}

// Scalar inlier predicate used by the mask pass (k5) — matches R1 behavior.
__device__ __forceinline__ float plane_dist(float4 pl, float px, float py, float pz) {
    return __fmaf_rn(pl.x, px, __fmaf_rn(pl.y, py, __fmaf_rn(pl.z, pz, pl.w)));
}

// ----------------------------- kernels ------------------------------------
__global__ void k0_init(const int* __restrict__ epoch_ptr) {
    int t = threadIdx.x;
    for (int i = t; i < NPLANES; i += blockDim.x) g_counts[i] = 0u;
    if (t == 0) {
        g_acc.sumX = 0.0; g_acc.sumY = 0.0; g_acc.sumZ = 0.0; g_acc.sumLog = 0.0;
        g_acc.cntM = 0ull;
        g_acc.gmaxBits = 0;
        g_acc.zmaxEnc = 0x007FFFFFu;   // enc(-inf)
        g_acc.zminEnc = 0xFF800000u;   // enc(+inf)
        g_acc.icnt = 0ull;
        g_acc.sumZc = 0.0;
        int epoch = epoch_ptr[0];
        float thf = (float)(0.025 - 0.001 * (double)epoch);
        g_acc.thresh = fmaxf(thf, 0.005f);
    }
}

__global__ void k1_stats(const float* __restrict__ fake, const float* __restrict__ real) {
    double sX = 0.0, sY = 0.0, sZ = 0.0, sL = 0.0;
    unsigned long long c = 0ull;
    float mx = 0.0f;
    for (int i = blockIdx.x * blockDim.x + threadIdx.x; i < HW; i += gridDim.x * blockDim.x) {
        int r = i / WIDTH;
        int col = i - r * WIDTH;
        float cc = (float)col - 334.081f;
        float rr = (float)r - 169.808f;
        float dr = real[i], df = fake[i];
        bool vr = (dr > 0.0f) && (dr < 65535.0f);
        bool vf = (df > 0.0f) && (df < 65535.0f);

        float fz = df / 1000.0f;
        float fxp = (fz * cc) / 460.585f;
        float fyp = (fz * rr) / 460.268f;
        float FXv = fxp * 1000.0f, FYv = fyp * 1000.0f, FZv = fz * 1000.0f;
        if (FXv == 0.0f) FXv = 1e-7f;
        if (FYv == 0.0f) FYv = 1e-7f;
        if (FZv == 0.0f) FZv = 1e-7f;
        float ox = vf ? FXv : 0.0f;
        float oy = vf ? FYv : 0.0f;
        float oz = vf ? FZv : 0.0f;
        g_cx[i] = ox; g_cy[i] = oy; g_cz[i] = oz;
        mx = fmaxf(mx, fmaxf(ox, fmaxf(oy, oz)));

        if (vr && vf) {
            float rz = dr / 1000.0f;
            float rxp = (rz * cc) / 460.585f;
            float ryp = (rz * rr) / 460.268f;
            float RXv = rxp * 1000.0f, RYv = ryp * 1000.0f, RZv = rz * 1000.0f;
            if (RXv == 0.0f) RXv = 1e-7f;
            if (RYv == 0.0f) RYv = 1e-7f;
            if (RZv == 0.0f) RZv = 1e-7f;
            float dx = RXv - FXv, dy = RYv - FYv, dz = RZv - FZv;
            sX += (double)dx * (double)dx;
            sY += (double)dy * (double)dy;
            sZ += (double)dz * (double)dz;
            float dl = logf(fabsf(RZv)) - logf(fabsf(FZv));
            sL += (double)dl * (double)dl;
            c++;
        }
    }
    sX = wred_add_d(sX); sY = wred_add_d(sY); sZ = wred_add_d(sZ); sL = wred_add_d(sL);
    c = wred_add_u(c);
    mx = wred_max_f(mx);
    if ((threadIdx.x & 31) == 0) {
        atomicAdd(&g_acc.sumX, sX);
        atomicAdd(&g_acc.sumY, sY);
        atomicAdd(&g_acc.sumZ, sZ);
        atomicAdd(&g_acc.sumLog, sL);
        atomicAdd(&g_acc.cntM, c);
        atomicMax(&g_acc.gmaxBits, __float_as_int(mx));  // mx >= 0 always
    }
}

__global__ void k2_planes() {
    int t = blockIdx.x * blockDim.x + threadIdx.x;
    if (t >= NPLANES) return;

    unsigned k10, k11, k20, k21;
    { unsigned x0 = 0u, x1 = 0u; tf2x32(0u, 42u, x0, x1); k10 = x0; k11 = x1; }
    { unsigned x0 = 0u, x1 = 1u; tf2x32(0u, 42u, x0, x1); k20 = x0; k21 = x1; }

    unsigned span = SPAN;
    unsigned mult = 65536u % span;
    mult = (mult * mult) % span;

    int ids[3];
    #pragma unroll
    for (int j = 0; j < 3; ++j) {
        unsigned i = (unsigned)(t * 3 + j);
        unsigned hi, lo;
        { unsigned x0 = 0u, x1 = i; tf2x32(k10, k11, x0, x1); hi = x0 ^ x1; }
        { unsigned x0 = 0u, x1 = i; tf2x32(k20, k21, x0, x1); lo = x0 ^ x1; }
        unsigned off = ((hi % span) * mult + (lo % span)) % span;
        ids[j] = (int)off;
    }

    float gmax = __int_as_float(g_acc.gmaxBits);
    float p0x = g_cx[ids[0]] / gmax, p0y = g_cy[ids[0]] / gmax, p0z = g_cz[ids[0]] / gmax;
    float p1x = g_cx[ids[1]] / gmax, p1y = g_cy[ids[1]] / gmax, p1z = g_cz[ids[1]] / gmax;
    float p2x = g_cx[ids[2]] / gmax, p2y = g_cy[ids[2]] / gmax, p2z = g_cz[ids[2]] / gmax;

    float ax = p1x - p0x, ay = p1y - p0y, az = p1z - p0z;
    float bx = p2x - p0x, by = p2y - p0y, bz = p2z - p0z;
    float nx = ay * bz - az * by;
    float ny = az * bx - ax * bz;
    float nz = ax * by - ay * bx;
    float nn = sqrtf(nx * nx + ny * ny + nz * nz);
    nx /= nn; ny /= nn; nz /= nn;
    float kk = -(nx * p1x + ny * p1y + nz * p1z);
    g_planes[t] = make_float4(nx, ny, nz, kk);
}

// Packed f32x2 inlier counting. gridDim = (450, 2); each y-group owns 512 planes;
// thread t handles planes ybase + t and ybase + 256 + t.
__global__ __launch_bounds__(K3_THREADS) void k3_count() {
    __shared__ __align__(8) float sx[K3_CHUNK];
    __shared__ __align__(8) float sy[K3_CHUNK];
    __shared__ __align__(8) float sz[K3_CHUNK];

    int base = blockIdx.x * K3_CHUNK;
    float gmax = __int_as_float(g_acc.gmaxBits);
    float th = g_acc.thresh;
    u64 NEGTH2 = pack2(-th * th, -th * th);

    // tile fill: each thread loads one float2 from each coord array
    {
        const float2* gx2 = (const float2*)(g_cx + base);
        const float2* gy2 = (const float2*)(g_cy + base);
        const float2* gz2 = (const float2*)(g_cz + base);
        int j = threadIdx.x;           // K3_CHUNK/2 == K3_THREADS
        float2 vx = gx2[j], vy = gy2[j], vz = gz2[j];
        ((float2*)sx)[j] = make_float2(vx.x / gmax, vx.y / gmax);
        ((float2*)sy)[j] = make_float2(vy.x / gmax, vy.y / gmax);
        ((float2*)sz)[j] = make_float2(vz.x / gmax, vz.y / gmax);
    }

    int pbase = blockIdx.y * 512;
    u64 PX[PPT], PY[PPT], PZ[PPT], PW[PPT];
    unsigned cnt[PPT];
    int pid[PPT];
    #pragma unroll
    for (int k = 0; k < PPT; ++k) {
        pid[k] = pbase + threadIdx.x + k * K3_THREADS;
        float4 pl = (pid[k] < NPLANES) ? g_planes[pid[k]]
                                       : make_float4(0.0f, 0.0f, 0.0f, 1e18f);
        PX[k] = pack2(pl.x, pl.x);
        PY[k] = pack2(pl.y, pl.y);
        PZ[k] = pack2(pl.z, pl.z);
        PW[k] = pack2(pl.w, pl.w);
        cnt[k] = 0u;
    }
    __syncthreads();

    const float2* sxv = (const float2*)sx;
    const float2* syv = (const float2*)sy;
    const float2* szv = (const float2*)sz;

    #pragma unroll 4
    for (int j = 0; j < K3_CHUNK / 2; ++j) {
        float2 vx = sxv[j], vy = syv[j], vz = szv[j];   // LDS.64 broadcast
        u64 X = pack2(vx.x, vx.y);
        u64 Y = pack2(vy.x, vy.y);
        u64 Z = pack2(vz.x, vz.y);
        #pragma unroll
        for (int k = 0; k < PPT; ++k) {
            u64 d = fma2(PX[k], X, fma2(PY[k], Y, fma2(PZ[k], Z, PW[k])));
            u64 u = fma2(d, d, NEGTH2);        // d*d - th*th; negative => inlier
            unsigned lo, hi;
            unpack2(u, lo, hi);
            cnt[k] += (lo >> 31) + (hi >> 31); // IADD3 fold
        }
    }

    #pragma unroll
    for (int k = 0; k < PPT; ++k)
        if (pid[k] < NPLANES) atomicAdd(&g_counts[pid[k]], cnt[k]);
}

__global__ void k4_select() {
    __shared__ int skey[1024];
    int t = threadIdx.x;
    int key = -1;
    if (t < NPLANES) {
        int c = (int)g_counts[t];
        int score = (c > MINPTS) ? c : -1;
        key = ((score + 1) << 12) | (1023 - t);   // first-index tiebreak
    }
    skey[t] = key;
    __syncthreads();
    for (int s = 512; s > 0; s >>= 1) {
        if (t < s) skey[t] = max(skey[t], skey[t + s]);
        __syncthreads();
    }
    if (t == 0) {
        int mk = skey[0];
        int best = 1023 - (mk & 0xFFF);
        g_acc.best = best;
        float4 bp = g_planes[best];
        g_acc.bestPlane = bp;
        float a = bp.x, b = bp.y, c = bp.z, d = bp.w;
        float n2 = a * a + b * b + c * c;
        float cos_t = c / sqrtf(n2);
        float sin_t = sqrtf((a * a + b * b) / n2);
        float sab = sqrtf(a * a + b * b);
        float u1 = b / sab;
        float u2 = -a / sab;
        g_acc.dz = d / c;
        g_acc.R20 = -u2 * sin_t;
        g_acc.R21 = u1 * sin_t;
        g_acc.R22 = cos_t;
    }
}

// Single pass: inlier mask -> zmax, zmin, count, sum(zc).
// Then below = zmax - mean(zc), above = mean(zc) - zmin (zmax/zmin are extrema
// over the same set, so the absolute values are sign-definite).
__global__ void k5_stats() {
    float gmax = __int_as_float(g_acc.gmaxBits);
    float th = g_acc.thresh;
    float4 bp = g_acc.bestPlane;
    float R20 = g_acc.R20, R21 = g_acc.R21, R22 = g_acc.R22, dz = g_acc.dz;
    const float INF = __int_as_float(0x7f800000);
    float zmx = -INF, zmn = INF;
    unsigned long long ic = 0ull;
    double sZc = 0.0;
    for (int i = blockIdx.x * blockDim.x + threadIdx.x; i < HW; i += gridDim.x * blockDim.x) {
        float px = g_cx[i] / gmax, py = g_cy[i] / gmax, pz = g_cz[i] / gmax;
        float d = plane_dist(bp, px, py, pz);
        if (fabsf(d) <= th) {
            float zc = __fmaf_rn(pz + dz, R22, __fmaf_rn(py, R21, px * R20));
            zmx = fmaxf(zmx, zc);
            zmn = fminf(zmn, zc);
            sZc += (double)zc;
            ic++;
        }
    }
    zmx = wred_max_f(zmx);
    zmn = wred_min_f(zmn);
    ic = wred_add_u(ic);
    sZc = wred_add_d(sZc);
    if ((threadIdx.x & 31) == 0) {
        atomicMax(&g_acc.zmaxEnc, encf(zmx));
        atomicMin(&g_acc.zminEnc, encf(zmn));
        atomicAdd(&g_acc.icnt, ic);
        atomicAdd(&g_acc.sumZc, sZc);
    }
}

__global__ void k6_final(float* __restrict__ out, int out_size) {
    unsigned long long cm = g_acc.cntM; if (cm < 1) cm = 1;
    double cnt = (double)cm;
    float lX = (float)sqrt(g_acc.sumX / cnt);
    float lY = (float)sqrt(g_acc.sumY / cnt);
    float lZ = (float)sqrt(g_acc.sumZ / cnt);
    float rmse_log = (float)(10000.0 * sqrt(g_acc.sumLog / cnt));
    float loss17 = rmse_log * fabsf(10.0f * (3.0f - expf(lX) - expf(lY) - expf(lZ)));

    unsigned long long icu = g_acc.icnt; if (icu < 1) icu = 1;
    double icnt = (double)icu;
    double meanZc = g_acc.sumZc / icnt;
    float zmax = decf(g_acc.zmaxEnc);
    float zmin = decf(g_acc.zminEnc);
    float below = (float)((double)zmax - meanZc);
    float above = (float)(meanZc - (double)zmin);
    if (above == 0.0f) above = 1e-7f;
    float pmdg = 1000.0f * (above + below);
    float loss_curv = loss17 + pmdg;

    float vals[7] = { rmse_log, lX, lY, lZ, pmdg, loss17, loss_curv };
    for (int i = 0; i < 7 && i < out_size; ++i) out[i] = vals[i];
}

// ----------------------------- launch -------------------------------------
extern "C" void kernel_launch(void* const* d_in, const int* in_sizes, int n_in,
                              void* d_out, int out_size) {
    const float* fake = (const float*)d_in[0];
    const float* real = (const float*)d_in[1];
    const int* epoch = (const int*)d_in[2];
    (void)in_sizes; (void)n_in;

    k0_init<<<1, 1024>>>(epoch);
    k1_stats<<<K1_BLOCKS, 256>>>(fake, real);
    k2_planes<<<(NPLANES + 255) / 256, 256>>>();
    dim3 g3(K3_XBLOCKS, K3_YBLOCKS);
    k3_count<<<g3, K3_THREADS>>>();
    k4_select<<<1, 1024>>>();
    k5_stats<<<K1_BLOCKS, 256>>>();
    k6_final<<<1, 1>>>((float*)d_out, out_size);
}